// round 17
// baseline (speedup 1.0000x reference)
#include <cuda_runtime.h>
#include <math.h>

#define T_LEN    8192
#define NDELAY   360
#define NTHREADS 512
#define PADA     424              // >= max lag 420 (pass taps), guard-free
#define PADB     848              // >= 2*max(L1,L2) = 840 (serial taps)
#define FULLMASK 0xffffffffu

// smem float layout: [PADA zeros | A=x 8192] [PADB zeros | B 8192]
#define OA 0
#define OB (OA + PADA + T_LEN)
#define SMEM_FLOATS (OB + PADB + T_LEN)

// ---------------------------------------------------------------------------
// y_t = x_t - a1*y_{t-L1} - a2*y_{t-L2}; exactly two taps (straight-through
// Gumbel one-hot is exactly hard in fp32), L1 = 61+m, L2 = 61+((m+1)%360).
// K=1 denominator squaring, fully general in (L1, L2):
//   y = x (1 - s) / (1 - s^2),   s = a1 z^-L1 + a2 z^-L2
//   pass:   B = (1-s) x                       (parallel, guard-free via pad)
//   serial: y_t = B_t + a1^2 y_{t-2L1} + 2a1a2 y_{t-L1-L2} + a2^2 y_{t-2L2}
//           rounds of width W = 2*min(L1,L2)  -> HALF the rounds of R16.
// Engine is R16's verbatim: 512 threads, in-place rounds on front-zero-padded
// smem, dual store (STS for later taps + STG to out), one code path for all m.
// ---------------------------------------------------------------------------

__device__ __forceinline__ float tanh_fast(float x) {
    x = fminf(fmaxf(x, -15.0f), 15.0f);
    float e = __expf(2.0f * x);
    return (e - 1.0f) * __frcp_rn(e + 1.0f);
}

__global__ void __launch_bounds__(NTHREADS)
ks_fused_kernel(const float* __restrict__ x,
                const float* __restrict__ gumbel,
                const float* __restrict__ delayp,
                const float* __restrict__ fb,
                const float* __restrict__ rc,
                float* __restrict__ out) {
    extern __shared__ float sm[];
    float* A = sm + OA + PADA;
    float* B = sm + OB + PADB;

    __shared__ float s_rv[16];
    __shared__ int   s_ri[16];
    __shared__ int   s_m;

    const int tid  = threadIdx.x;
    const int row  = blockIdx.x;
    const int lane = tid & 31;
    const int wid  = tid >> 5;
    const float* xr = x + (size_t)row * T_LEN;
    float*       yr = out + (size_t)row * T_LEN;

    // --- stage x (coalesced float4); setup below hides the LDG latency ---
    {
        const float4* x4 = (const float4*)xr;
        float4* a4 = (float4*)A;
#pragma unroll
        for (int i = 0; i < T_LEN / 4 / NTHREADS; i++)
            a4[tid + i * NTHREADS] = x4[tid + i * NTHREADS];
        if (tid < PADA) sm[OA + tid] = 0.0f;
        if (tid < PADB) sm[OB + tid] = 0.0f;
        if (tid < PADB - NTHREADS) sm[OB + NTHREADS + tid] = 0.0f;
    }

    // --- argmax over 360 logits (first-index tie-break) ---
    float lv = -INFINITY;
    int   li = tid;
    if (tid < NDELAY) lv = delayp[tid] + gumbel[tid];
#pragma unroll
    for (int off = 16; off > 0; off >>= 1) {
        float ov = __shfl_down_sync(FULLMASK, lv, off);
        int   oi = __shfl_down_sync(FULLMASK, li, off);
        if (ov > lv || (ov == lv && oi < li)) { lv = ov; li = oi; }
    }
    if (lane == 0) { s_rv[wid] = lv; s_ri[wid] = li; }

    // --- scalar coefficients (redundant per thread; fast intrinsics) ---
    float k1 = tanh_fast(tanh_fast(rc[0]));
    float k2 = tanh_fast(tanh_fast(rc[1]));
    float a1 = k1 * (1.0f - k2);
    float a2 = fminf(fmaxf(k2, -0.999f), 0.999f);
    float bound = 0.999f - fabsf(a2);
    a1 = fminf(fmaxf(a1, -bound), bound);
    float sg = __frcp_rn(1.0f + __expf(-fb[0]));
    float g  = __powf(sg, 0.45f);
    a1 *= g;
    a2 *= g;

    __syncthreads();
    if (tid < 32) {
        lv = (lane < 16) ? s_rv[lane] : -INFINITY;
        li = (lane < 16) ? s_ri[lane] : 0x7fffffff;
#pragma unroll
        for (int off = 8; off > 0; off >>= 1) {
            float ov = __shfl_down_sync(FULLMASK, lv, off);
            int   oi = __shfl_down_sync(FULLMASK, li, off);
            if (ov > lv || (ov == lv && oi < li)) { lv = ov; li = oi; }
        }
        if (lane == 0) s_m = li;
    }
    __syncthreads();   // staging + pads + argmax complete

    const int m  = s_m;
    const int L1 = 61 + m;
    const int L2 = 61 + ((m + 1) % NDELAY);
    const int C  = (L1 < L2) ? L1 : L2;

    // --- pass: B = (1 - s) A  (guard-free; A pad >= max lag) ---
#pragma unroll
    for (int i = 0; i < T_LEN / NTHREADS; i++) {
        const int t = i * NTHREADS + tid;
        float w = fmaf(-a1, A[t - L1], A[t]);
        B[t] = fmaf(-a2, A[t - L2], w);
    }
    __syncthreads();

    // --- serial rounds on B, width W = 2C; dual store STS + STG ---
    {
        const float q0 = a1 * a1;
        const float q1 = 2.0f * a1 * a2;
        const float q2 = a2 * a2;
        const int   g0 = 2 * L1;
        const int   g1 = L1 + L2;
        const int   g2 = 2 * L2;
        const int   W  = 2 * C;

        for (int s0 = 0; s0 < T_LEN; s0 += W) {
            const int lim = (s0 + W < T_LEN) ? (s0 + W) : T_LEN;
            for (int t = s0 + tid; t < lim; t += NTHREADS) {
                float y = fmaf(q0, B[t - g0], B[t]);
                y = fmaf(q1, B[t - g1], y);
                y = fmaf(q2, B[t - g2], y);
                B[t]  = y;
                yr[t] = y;
            }
            __syncthreads();
        }
    }
}

// ---------------------------------------------------------------------------
// inputs: excitation[128*8192] f32, gumbel[360], delay_param[360],
//         feedback_gain[1], reflection_coeffs[2]; output f32 [128*8192]
// ---------------------------------------------------------------------------
extern "C" void kernel_launch(void* const* d_in, const int* in_sizes, int n_in,
                              void* d_out, int out_size) {
    const float* x      = (const float*)d_in[0];
    const float* gumbel = (const float*)d_in[1];
    const float* delayp = (const float*)d_in[2];
    const float* fb     = (const float*)d_in[3];
    const float* rc     = (const float*)d_in[4];
    float* out = (float*)d_out;

    const int rows = in_sizes[0] / T_LEN;
    const int smem_bytes = SMEM_FLOATS * sizeof(float);

    cudaFuncSetAttribute(ks_fused_kernel,
                         cudaFuncAttributeMaxDynamicSharedMemorySize, smem_bytes);
    ks_fused_kernel<<<rows, NTHREADS, smem_bytes>>>(x, gumbel, delayp, fb, rc, out);
}